// round 6
// baseline (speedup 1.0000x reference)
#include <cuda_runtime.h>
#include <cuda_bf16.h>
#include <cstdint>

// Problem: S=8, N=2048, D=256
//   qt0[s,j,d] = sum_e tensor0[s,j,e] * kernel[d,e]
//   out[s,i,j] = sum_d tensor1[s,i,d] * qt0[s,j,d] + bias
//
// 3-term split-fp32 as ONE plain bf16 NT GEMM over K3 = 3*256 = 768:
//   x = h + l  (h = trunc-to-bf16, l = rn(x - h))
//   A rows stored [h | l | h], B rows stored [h' | h' | l']
//   => dot = h*h' + l*h' + h*l'   (rel err ~2^-17; l*l' term negligible)
// Hot loop: cp.async + ldmatrix + mma.sync.m16n8k16 (sm_103 base ISA), no math.

#define BM 128
#define BN 256
#define NTHREADS 256
#define STAGES 4
#define ROWB 80                     // padded smem row stride (32 bf16 = 64B + 16B)
#define SA_BYTES (BM * ROWB)        // 10240
#define SB_BYTES (BN * ROWB)        // 20480
#define STAGE_BYTES (SA_BYTES + SB_BYTES)
#define SMEM_BYTES (STAGES * STAGE_BYTES)   // 122880

static const int S_ = 8;
static const int N_ = 2048;
static const int D_ = 256;
static const int K3 = 768;          // 3*D

// device scratch (no allocs allowed): ~76 MB total
__device__ __nv_bfloat16 g_t0hl[8 * 2048 * 768];
__device__ __nv_bfloat16 g_t1hl[8 * 2048 * 768];
__device__ __nv_bfloat16 g_khl[256 * 768];
__device__ __nv_bfloat16 g_qt0hl[8 * 2048 * 768];

__device__ __forceinline__ uint32_t smem_u32(const void* p) {
    uint32_t a;
    asm("{ .reg .u64 t; cvta.to.shared.u64 t, %1; cvt.u32.u64 %0, t; }" : "=r"(a) : "l"(p));
    return a;
}
__device__ __forceinline__ void ldsm4(uint32_t* r, uint32_t addr) {
    asm volatile("ldmatrix.sync.aligned.m8n8.x4.shared.b16 {%0,%1,%2,%3}, [%4];"
                 : "=r"(r[0]), "=r"(r[1]), "=r"(r[2]), "=r"(r[3]) : "r"(addr));
}
__device__ __forceinline__ void mma16816(float* c, const uint32_t* a, uint32_t b0, uint32_t b1) {
    asm volatile("mma.sync.aligned.m16n8k16.row.col.f32.bf16.bf16.f32 "
                 "{%0,%1,%2,%3}, {%4,%5,%6,%7}, {%8,%9}, {%0,%1,%2,%3};"
                 : "+f"(c[0]), "+f"(c[1]), "+f"(c[2]), "+f"(c[3])
                 : "r"(a[0]), "r"(a[1]), "r"(a[2]), "r"(a[3]), "r"(b0), "r"(b1));
}
__device__ __forceinline__ uint32_t cvt_bf16x2(float hi, float lo) {
    uint32_t d;
    asm("cvt.rn.bf16x2.f32 %0, %1, %2;" : "=r"(d) : "f"(hi), "f"(lo));
    return d;
}
__device__ __forceinline__ void cp16(uint32_t dst, const void* src) {
    asm volatile("cp.async.cg.shared.global [%0], [%1], 16;" :: "r"(dst), "l"(src));
}

// ---- pre-pass: fp32 [rows, D] -> bf16 [rows, 3D]; segment layout via quad offsets.
// A-operands: [h | l | h]  -> loff4 = Dq,   h2off4 = 2*Dq
// B-operands: [h | h | l]  -> loff4 = 2*Dq, h2off4 = Dq
__global__ void split3_kernel(const float* __restrict__ src,
                              __nv_bfloat16* __restrict__ dst,
                              int total4, int Dq, int loff4, int h2off4)
{
    int idx = blockIdx.x * blockDim.x + threadIdx.x;
    if (idx >= total4) return;
    int row = idx / Dq;
    int g = idx - row * Dq;
    float4 v = ((const float4*)src)[idx];
    uint32_t xb = __float_as_uint(v.x), yb = __float_as_uint(v.y);
    uint32_t zb = __float_as_uint(v.z), wb = __float_as_uint(v.w);
    uint2 hp = make_uint2(__byte_perm(xb, yb, 0x7632), __byte_perm(zb, wb, 0x7632));
    float l0 = v.x - __uint_as_float(xb & 0xFFFF0000u);
    float l1 = v.y - __uint_as_float(yb & 0xFFFF0000u);
    float l2 = v.z - __uint_as_float(zb & 0xFFFF0000u);
    float l3 = v.w - __uint_as_float(wb & 0xFFFF0000u);
    uint2 lp = make_uint2(cvt_bf16x2(l1, l0), cvt_bf16x2(l3, l2));
    uint2* drow = (uint2*)(dst + (long)row * (3 * Dq * 4));
    drow[g] = hp;
    drow[loff4 + g] = lp;
    drow[h2off4 + g] = hp;
}

// ---- main GEMM: C[b,m,n] = sum_k A[b,m,k]*B[b,n,k], A/B bf16 [.., rows, K] ----
// epi_hl == 0: C fp32 [.., M, ldC], + bias.
// epi_hl == 1: C bf16 rows of 3*ldC = [h(ldC) | h(ldC) | l(ldC)]  (single batch).
__global__ __launch_bounds__(NTHREADS, 1)
void gemm_bf16_kernel(const __nv_bfloat16* __restrict__ A,
                      const __nv_bfloat16* __restrict__ B,
                      void* __restrict__ Cv,
                      int K, int ldC,
                      long strideA, long strideB, long strideC,
                      const float* __restrict__ bias_ptr, int epi_hl)
{
    extern __shared__ __align__(16) char smem[];
    const uint32_t sbase = smem_u32(smem);

    const int tid  = threadIdx.x;
    const int lane = tid & 31;
    const int wid  = tid >> 5;        // 0..7
    const int wm   = wid & 1;         // 2 warps along M (64 rows)
    const int wn   = wid >> 1;        // 4 warps along N (64 cols)
    const int m0   = blockIdx.y * BM;
    const int n0   = blockIdx.x * BN;
    const int b    = blockIdx.z;

    const __nv_bfloat16* Ab = A + (long)b * strideA + (long)m0 * K;
    const __nv_bfloat16* Bb = B + (long)b * strideB + (long)n0 * K;

    float acc[4][8][4];
    #pragma unroll
    for (int mi = 0; mi < 4; mi++)
        #pragma unroll
        for (int ni = 0; ni < 8; ni++)
            #pragma unroll
            for (int j = 0; j < 4; j++)
                acc[mi][ni][j] = 0.0f;

    const int nchunk = K / 32;        // 64B of K per chunk

    auto issue_stage = [&](int slot, int kb) {
        uint32_t stA = sbase + slot * STAGE_BYTES;
        #pragma unroll
        for (int i = 0; i < 2; i++) {
            int q = tid + NTHREADS * i;
            int row = q >> 2, qd = q & 3;
            cp16(stA + row * ROWB + qd * 16,
                 (const char*)(Ab + (long)row * K) + kb + qd * 16);
        }
        uint32_t stB = stA + SA_BYTES;
        #pragma unroll
        for (int i = 0; i < 4; i++) {
            int q = tid + NTHREADS * i;
            int row = q >> 2, qd = q & 3;
            cp16(stB + row * ROWB + qd * 16,
                 (const char*)(Bb + (long)row * K) + kb + qd * 16);
        }
        asm volatile("cp.async.commit_group;" ::: "memory");
    };

    issue_stage(0, 0);
    issue_stage(1, 64);
    issue_stage(2, 128);

    const uint32_t lmOff = (uint32_t)((lane & 15) * ROWB + (lane >> 4) * 16);
    const uint32_t aOff = (uint32_t)(wm * 64 * ROWB) + lmOff;
    const uint32_t bOff = (uint32_t)(SA_BYTES + wn * 64 * ROWB) + lmOff;

    for (int c = 0; c < nchunk; c++) {
        asm volatile("cp.async.wait_group 2;" ::: "memory");
        __syncthreads();

        if (c + 3 < nchunk) issue_stage((c + 3) & (STAGES - 1), (c + 3) * 64);
        else asm volatile("cp.async.commit_group;" ::: "memory");

        const uint32_t st = sbase + (c & (STAGES - 1)) * STAGE_BYTES;
        const uint32_t sA = st + aOff;
        const uint32_t sB = st + bOff;

        #pragma unroll
        for (int ks = 0; ks < 2; ks++) {
            const uint32_t ko = ks * 32;   // 16 bf16 = 32B
            uint32_t aF[4][4], bF[4][4];
            #pragma unroll
            for (int mi = 0; mi < 4; mi++) ldsm4(aF[mi], sA + mi * 16 * ROWB + ko);
            #pragma unroll
            for (int p = 0; p < 4; p++)   ldsm4(bF[p], sB + p * 16 * ROWB + ko);

            #pragma unroll
            for (int mi = 0; mi < 4; mi++) {
                #pragma unroll
                for (int ni = 0; ni < 8; ni++) {
                    const int p = ni >> 1, o = ni & 1;
                    mma16816(acc[mi][ni], aF[mi], bF[p][o], bF[p][o + 2]);
                }
            }
        }
    }

    // ---------------- epilogue ----------------
    const int rbase = wm * 64 + (lane >> 2);
    const int cbase = wn * 64 + (lane & 3) * 2;

    if (!epi_hl) {
        float* Cb = (float*)Cv + (long)b * strideC;
        const float bv = bias_ptr ? bias_ptr[0] : 0.0f;
        #pragma unroll
        for (int mi = 0; mi < 4; mi++) {
            #pragma unroll
            for (int ni = 0; ni < 8; ni++) {
                const int r = m0 + rbase + mi * 16;
                const int cc = n0 + cbase + ni * 8;
                float2 v0 = make_float2(acc[mi][ni][0] + bv, acc[mi][ni][1] + bv);
                float2 v1 = make_float2(acc[mi][ni][2] + bv, acc[mi][ni][3] + bv);
                *(float2*)(Cb + (long)r * ldC + cc)       = v0;
                *(float2*)(Cb + (long)(r + 8) * ldC + cc) = v1;
            }
        }
    } else {
        // bf16 rows of 3*ldC: [h | h | l]
        __nv_bfloat16* Cb = (__nv_bfloat16*)Cv;
        #pragma unroll
        for (int mi = 0; mi < 4; mi++) {
            #pragma unroll
            for (int ni = 0; ni < 8; ni++) {
                const int cc = n0 + cbase + ni * 8;
                #pragma unroll
                for (int half = 0; half < 2; half++) {
                    const int r = m0 + rbase + mi * 16 + half * 8;
                    float f0 = acc[mi][ni][2 * half + 0];
                    float f1 = acc[mi][ni][2 * half + 1];
                    uint32_t b0 = __float_as_uint(f0), b1 = __float_as_uint(f1);
                    uint32_t hp = __byte_perm(b0, b1, 0x7632);
                    float l0 = f0 - __uint_as_float(b0 & 0xFFFF0000u);
                    float l1 = f1 - __uint_as_float(b1 & 0xFFFF0000u);
                    uint32_t lp = cvt_bf16x2(l1, l0);
                    __nv_bfloat16* row = Cb + (long)r * (3 * ldC);
                    *(uint32_t*)(row + cc)            = hp;
                    *(uint32_t*)(row + ldC + cc)      = hp;
                    *(uint32_t*)(row + 2 * ldC + cc)  = lp;
                }
            }
        }
    }
}

extern "C" void kernel_launch(void* const* d_in, const int* in_sizes, int n_in,
                              void* d_out, int out_size)
{
    const float* tensor0 = (const float*)d_in[0];  // [S, N, D]
    const float* tensor1 = (const float*)d_in[1];  // [S, N, D]
    const float* kernelw = (const float*)d_in[2];  // [D, D]
    const float* bias    = (const float*)d_in[3];  // [1]
    float* out = (float*)d_out;                    // [S, N, N]

    __nv_bfloat16 *t0hl, *t1hl, *khl, *qt0hl;
    cudaGetSymbolAddress((void**)&t0hl, g_t0hl);
    cudaGetSymbolAddress((void**)&t1hl, g_t1hl);
    cudaGetSymbolAddress((void**)&khl, g_khl);
    cudaGetSymbolAddress((void**)&qt0hl, g_qt0hl);

    cudaFuncSetAttribute(gemm_bf16_kernel,
                         cudaFuncAttributeMaxDynamicSharedMemorySize, SMEM_BYTES);

    const int Dq = D_ / 4;   // 64 quads per segment
    // pre-pass: A-operands [h|l|h]; B-operand (kernel) [h|h|l]
    {
        int t4a = S_ * N_ * D_ / 4;                 // 1048576
        split3_kernel<<<(t4a + 255) / 256, 256>>>(tensor0, t0hl, t4a, Dq, Dq, 2 * Dq);
        split3_kernel<<<(t4a + 255) / 256, 256>>>(tensor1, t1hl, t4a, Dq, Dq, 2 * Dq);
        int t4k = D_ * D_ / 4;                      // 16384
        split3_kernel<<<(t4k + 255) / 256, 256>>>(kernelw, khl, t4k, Dq, 2 * Dq, Dq);
    }

    // GEMM1: qt0 = t0 @ kernel^T, output written as [h|h|l] bf16 (K3 layout)
    {
        dim3 grid(D_ / BN, (S_ * N_) / BM, 1);      // (1, 128, 1)
        gemm_bf16_kernel<<<grid, NTHREADS, SMEM_BYTES>>>(
            t0hl, khl, qt0hl, K3, D_, 0, 0, 0, nullptr, 1);
    }
    // GEMM2: out[s,i,j] = sum t1hl[s,i,:]*qt0hl[s,j,:] + bias
    {
        dim3 grid(N_ / BN, N_ / BM, S_);            // (8, 16, 8)
        gemm_bf16_kernel<<<grid, NTHREADS, SMEM_BYTES>>>(
            t1hl, qt0hl, out, K3, N_,
            (long)N_ * K3, (long)N_ * K3, (long)N_ * N_, bias, 0);
    }
}

// round 7
// speedup vs baseline: 1.1755x; 1.1755x over previous
#include <cuda_runtime.h>
#include <cuda_bf16.h>
#include <cstdint>

// Problem: S=8, N=2048, D=256
//   qt0[s,j,d] = sum_e tensor0[s,j,e] * kernel[d,e]
//   out[s,i,j] = sum_d tensor1[s,i,d] * qt0[s,j,d] + bias
//
// Split fp32 x = h + l (h = trunc-to-bf16, l = rn(x-h)); gmem stores rows as
// [h(256) | l(256)] bf16 (K2 = 512). Hot loop loads Ah/Al/Bh/Bl tiles and does
//   x*y ~= Ah*Bh + Al*Bh + Ah*Bl   (rel err ~2^-17)
// via mma.sync.m16n8k16 bf16 (sm_103 base ISA), cp.async double-buffered.

#define BM 128
#define BN 128
#define NTHREADS 256
#define STAGES 2
#define ROWB 80                      // padded smem row stride (32 bf16 = 64B + 16B)
#define TILE_B (128 * ROWB)          // 10240 per tile
#define STAGE_BYTES (4 * TILE_B)     // Ah, Al, Bh, Bl
#define SMEM_BYTES (STAGES * STAGE_BYTES)   // 81920

static const int S_ = 8;
static const int N_ = 2048;
static const int D_ = 256;
static const int K2 = 512;           // [h | l]

// device scratch (no allocs allowed): 48.25 MB
__device__ __nv_bfloat16 g_t0hl[8 * 2048 * 512];
__device__ __nv_bfloat16 g_t1hl[8 * 2048 * 512];
__device__ __nv_bfloat16 g_khl[256 * 512];
__device__ __nv_bfloat16 g_qt0hl[8 * 2048 * 512];

__device__ __forceinline__ uint32_t smem_u32(const void* p) {
    uint32_t a;
    asm("{ .reg .u64 t; cvta.to.shared.u64 t, %1; cvt.u32.u64 %0, t; }" : "=r"(a) : "l"(p));
    return a;
}
__device__ __forceinline__ void ldsm4(uint32_t* r, uint32_t addr) {
    asm volatile("ldmatrix.sync.aligned.m8n8.x4.shared.b16 {%0,%1,%2,%3}, [%4];"
                 : "=r"(r[0]), "=r"(r[1]), "=r"(r[2]), "=r"(r[3]) : "r"(addr));
}
__device__ __forceinline__ void mma16816(float* c, const uint32_t* a, uint32_t b0, uint32_t b1) {
    asm volatile("mma.sync.aligned.m16n8k16.row.col.f32.bf16.bf16.f32 "
                 "{%0,%1,%2,%3}, {%4,%5,%6,%7}, {%8,%9}, {%0,%1,%2,%3};"
                 : "+f"(c[0]), "+f"(c[1]), "+f"(c[2]), "+f"(c[3])
                 : "r"(a[0]), "r"(a[1]), "r"(a[2]), "r"(a[3]), "r"(b0), "r"(b1));
}
__device__ __forceinline__ uint32_t cvt_bf16x2(float hi, float lo) {
    uint32_t d;
    asm("cvt.rn.bf16x2.f32 %0, %1, %2;" : "=r"(d) : "f"(hi), "f"(lo));
    return d;
}
__device__ __forceinline__ void cp16(uint32_t dst, const void* src) {
    asm volatile("cp.async.cg.shared.global [%0], [%1], 16;" :: "r"(dst), "l"(src));
}

// ---- pre-pass: fp32 [rows, D] -> bf16 [rows, 2D] = [h | l] ----
__global__ void split_hl_kernel(const float* __restrict__ src,
                                __nv_bfloat16* __restrict__ dst,
                                int total4, int Dq)
{
    int idx = blockIdx.x * blockDim.x + threadIdx.x;
    if (idx >= total4) return;
    int row = idx / Dq;
    int g = idx - row * Dq;
    float4 v = ((const float4*)src)[idx];
    uint32_t xb = __float_as_uint(v.x), yb = __float_as_uint(v.y);
    uint32_t zb = __float_as_uint(v.z), wb = __float_as_uint(v.w);
    uint2 hp = make_uint2(__byte_perm(xb, yb, 0x7632), __byte_perm(zb, wb, 0x7632));
    float l0 = v.x - __uint_as_float(xb & 0xFFFF0000u);
    float l1 = v.y - __uint_as_float(yb & 0xFFFF0000u);
    float l2 = v.z - __uint_as_float(zb & 0xFFFF0000u);
    float l3 = v.w - __uint_as_float(wb & 0xFFFF0000u);
    uint2 lp = make_uint2(cvt_bf16x2(l1, l0), cvt_bf16x2(l3, l2));
    uint2* drow = (uint2*)(dst + (long)row * (2 * Dq * 4));
    drow[g] = hp;
    drow[Dq + g] = lp;
}

// ---- GEMM: C[b,m,n] = sum_d A[b,m,d]*B[b,n,d]; A,B bf16 [rows, K2] = [h|l] ----
// epi_hl == 0: C fp32 [.., M, ldC], + bias.
// epi_hl == 1: C bf16 rows of 2*ldC = [h(ldC) | l(ldC)] (single batch).
__global__ __launch_bounds__(NTHREADS, 2)
void gemm_hl_kernel(const __nv_bfloat16* __restrict__ A,
                    const __nv_bfloat16* __restrict__ B,
                    void* __restrict__ Cv,
                    int ldC,
                    long strideA, long strideB, long strideC,
                    const float* __restrict__ bias_ptr, int epi_hl)
{
    extern __shared__ __align__(16) char smem[];
    const uint32_t sbase = smem_u32(smem);

    const int tid  = threadIdx.x;
    const int lane = tid & 31;
    const int wid  = tid >> 5;        // 0..7
    const int wm   = wid & 1;         // 2 warps along M (64 rows)
    const int wn   = wid >> 1;        // 4 warps along N (32 cols)
    const int m0   = blockIdx.y * BM;
    const int n0   = blockIdx.x * BN;
    const int b    = blockIdx.z;

    const char* Ab = (const char*)(A + (long)b * strideA + (long)m0 * K2);
    const char* Bb = (const char*)(B + (long)b * strideB + (long)n0 * K2);
    const int rowBytes = K2 * 2;      // 1024
    const int lHalf = D_ * 2;         // 512: byte offset of l segment within a row

    float acc[4][4][4];
    #pragma unroll
    for (int mi = 0; mi < 4; mi++)
        #pragma unroll
        for (int nf = 0; nf < 4; nf++)
            #pragma unroll
            for (int j = 0; j < 4; j++)
                acc[mi][nf][j] = 0.0f;

    const int nchunk = D_ / 32;       // 8: 32 fp32-K per chunk (64B h + 64B l)

    // issue one stage: Ah, Al, Bh, Bl tiles (128 rows x 64B each)
    auto issue_stage = [&](int slot, int c) {
        const int kb = c * 64;
        const uint32_t st = sbase + slot * STAGE_BYTES;
        #pragma unroll
        for (int i = 0; i < 2; i++) {
            int q = tid + NTHREADS * i;
            int row = q >> 2, qd = (q & 3) * 16;
            const char* arow = Ab + (long)row * rowBytes + kb + qd;
            const char* brow = Bb + (long)row * rowBytes + kb + qd;
            uint32_t so = row * ROWB + qd;
            cp16(st + so,              arow);          // Ah
            cp16(st + TILE_B + so,     arow + lHalf);  // Al
            cp16(st + 2 * TILE_B + so, brow);          // Bh
            cp16(st + 3 * TILE_B + so, brow + lHalf);  // Bl
        }
        asm volatile("cp.async.commit_group;" ::: "memory");
    };

    issue_stage(0, 0);

    const uint32_t lmOff = (uint32_t)((lane & 15) * ROWB + (lane >> 4) * 16);
    const uint32_t aOff = (uint32_t)(wm * 64 * ROWB) + lmOff;
    const uint32_t bOff = (uint32_t)(2 * TILE_B + wn * 32 * ROWB) + lmOff;

    for (int c = 0; c < nchunk; c++) {
        if (c + 1 < nchunk) {
            issue_stage((c + 1) & 1, c + 1);
            asm volatile("cp.async.wait_group 1;" ::: "memory");
        } else {
            asm volatile("cp.async.wait_group 0;" ::: "memory");
        }
        __syncthreads();              // stage c visible to all

        const uint32_t st = sbase + (c & 1) * STAGE_BYTES;
        const uint32_t sA = st + aOff;
        const uint32_t sB = st + bOff;

        #pragma unroll
        for (int ks = 0; ks < 2; ks++) {
            const uint32_t ko = ks * 32;   // 16 bf16 = 32B
            uint32_t aH[4][4], aL[4][4], bH[2][4], bL[2][4];
            #pragma unroll
            for (int mi = 0; mi < 4; mi++) ldsm4(aH[mi], sA + mi * 16 * ROWB + ko);
            #pragma unroll
            for (int nb = 0; nb < 2; nb++) ldsm4(bH[nb], sB + nb * 16 * ROWB + ko);
            #pragma unroll
            for (int mi = 0; mi < 4; mi++) ldsm4(aL[mi], sA + TILE_B + mi * 16 * ROWB + ko);
            #pragma unroll
            for (int nb = 0; nb < 2; nb++) ldsm4(bL[nb], sB + TILE_B + nb * 16 * ROWB + ko);

            #pragma unroll
            for (int mi = 0; mi < 4; mi++) {
                #pragma unroll
                for (int nf = 0; nf < 4; nf++) {
                    const int nb = nf >> 1, o = nf & 1;
                    mma16816(acc[mi][nf], aH[mi], bH[nb][o], bH[nb][o + 2]);  // h*h
                    mma16816(acc[mi][nf], aL[mi], bH[nb][o], bH[nb][o + 2]);  // l*h
                    mma16816(acc[mi][nf], aH[mi], bL[nb][o], bL[nb][o + 2]);  // h*l
                }
            }
        }
        __syncthreads();              // all reads of stage c done before overwrite
    }

    // ---------------- epilogue ----------------
    const int rbase = wm * 64 + (lane >> 2);
    const int cbase = wn * 32 + (lane & 3) * 2;

    if (!epi_hl) {
        float* Cb = (float*)Cv + (long)b * strideC;
        const float bv = bias_ptr ? bias_ptr[0] : 0.0f;
        #pragma unroll
        for (int mi = 0; mi < 4; mi++) {
            #pragma unroll
            for (int nf = 0; nf < 4; nf++) {
                const int r = m0 + rbase + mi * 16;
                const int cc = n0 + cbase + nf * 8;
                float2 v0 = make_float2(acc[mi][nf][0] + bv, acc[mi][nf][1] + bv);
                float2 v1 = make_float2(acc[mi][nf][2] + bv, acc[mi][nf][3] + bv);
                *(float2*)(Cb + (long)r * ldC + cc)       = v0;
                *(float2*)(Cb + (long)(r + 8) * ldC + cc) = v1;
            }
        }
    } else {
        // bf16 rows of 2*ldC: [h | l]
        __nv_bfloat16* Cb = (__nv_bfloat16*)Cv;
        #pragma unroll
        for (int mi = 0; mi < 4; mi++) {
            #pragma unroll
            for (int nf = 0; nf < 4; nf++) {
                const int cc = n0 + cbase + nf * 8;
                #pragma unroll
                for (int half = 0; half < 2; half++) {
                    const int r = m0 + rbase + mi * 16 + half * 8;
                    float f0 = acc[mi][nf][2 * half + 0];
                    float f1 = acc[mi][nf][2 * half + 1];
                    uint32_t b0 = __float_as_uint(f0), b1 = __float_as_uint(f1);
                    uint32_t hp = __byte_perm(b0, b1, 0x7632);
                    float l0 = f0 - __uint_as_float(b0 & 0xFFFF0000u);
                    float l1 = f1 - __uint_as_float(b1 & 0xFFFF0000u);
                    uint32_t lp = cvt_bf16x2(l1, l0);
                    __nv_bfloat16* row = Cb + (long)r * (2 * ldC);
                    *(uint32_t*)(row + cc)       = hp;
                    *(uint32_t*)(row + ldC + cc) = lp;
                }
            }
        }
    }
}

extern "C" void kernel_launch(void* const* d_in, const int* in_sizes, int n_in,
                              void* d_out, int out_size)
{
    const float* tensor0 = (const float*)d_in[0];  // [S, N, D]
    const float* tensor1 = (const float*)d_in[1];  // [S, N, D]
    const float* kernelw = (const float*)d_in[2];  // [D, D]
    const float* bias    = (const float*)d_in[3];  // [1]
    float* out = (float*)d_out;                    // [S, N, N]

    __nv_bfloat16 *t0hl, *t1hl, *khl, *qt0hl;
    cudaGetSymbolAddress((void**)&t0hl, g_t0hl);
    cudaGetSymbolAddress((void**)&t1hl, g_t1hl);
    cudaGetSymbolAddress((void**)&khl, g_khl);
    cudaGetSymbolAddress((void**)&qt0hl, g_qt0hl);

    cudaFuncSetAttribute(gemm_hl_kernel,
                         cudaFuncAttributeMaxDynamicSharedMemorySize, SMEM_BYTES);

    const int Dq = D_ / 4;
    // pre-pass: fp32 -> [h|l]
    {
        int t4a = S_ * N_ * D_ / 4;
        split_hl_kernel<<<(t4a + 255) / 256, 256>>>(tensor0, t0hl, t4a, Dq);
        split_hl_kernel<<<(t4a + 255) / 256, 256>>>(tensor1, t1hl, t4a, Dq);
        int t4k = D_ * D_ / 4;
        split_hl_kernel<<<(t4k + 255) / 256, 256>>>(kernelw, khl, t4k, Dq);
    }

    // GEMM1: qt0 = t0 @ kernel^T, output as [h|l] bf16; M=16384, N'=256
    {
        dim3 grid(D_ / BN, (S_ * N_) / BM, 1);      // (2, 128, 1)
        gemm_hl_kernel<<<grid, NTHREADS, SMEM_BYTES>>>(
            t0hl, khl, qt0hl, D_, 0, 0, 0, nullptr, 1);
    }
    // GEMM2: out = t1 @ qt0^T + bias; 2048x2048 x8
    {
        dim3 grid(N_ / BN, N_ / BM, S_);            // (16, 16, 8)
        gemm_hl_kernel<<<grid, NTHREADS, SMEM_BYTES>>>(
            t1hl, qt0hl, out, N_,
            (long)N_ * K2, (long)N_ * K2, (long)N_ * N_, bias, 0);
    }
}